// round 1
// baseline (speedup 1.0000x reference)
#include <cuda_runtime.h>
#include <cstdint>

// Problem constants: B=8, C=64, H=W=128, 3x3 window, zero padding.
#define C 64
#define H 128
#define W 128
#define TH 16          // tile rows
#define TW 32          // tile cols
#define HR (TH + 2)    // halo rows = 18
#define WC (TW + 2)    // halo cols = 34
#define HALO_ELEMS (HR * WC)            // 612
#define SMEM_FLOATS (C * HALO_ELEMS)    // 39168
#define SMEM_BYTES (SMEM_FLOATS * 4)    // 156672

__global__ void __launch_bounds__(512, 1)
refine_kernel(const float* __restrict__ fe,
              const float* __restrict__ fu,
              float* __restrict__ out) {
    extern __shared__ float smf[];  // [C][HALO_ELEMS]

    const int tx = threadIdx.x;       // 0..31
    const int ty = threadIdx.y;       // 0..15
    const int tid = ty * 32 + tx;     // 0..511

    const int col0 = blockIdx.x * TW;
    const int row0 = blockIdx.y * TH;
    const int b    = blockIdx.z;

    const size_t plane = (size_t)H * W;
    const float* fub = fu + (size_t)b * C * plane;

    // ---- Load fused halo tile (all 64 channels) into SMEM, zero-padded ----
    #pragma unroll 4
    for (int c = 0; c < C; ++c) {
        const float* src = fub + (size_t)c * plane;
        float* dst = smf + c * HALO_ELEMS;
        #pragma unroll
        for (int t = 0; t < 2; ++t) {
            int i = tid + t * 512;
            if (i < HALO_ELEMS) {
                int lr = i / WC;
                int lc = i - lr * WC;
                int gr = row0 - 1 + lr;
                int gc = col0 - 1 + lc;
                float v = 0.0f;
                if ((unsigned)gr < (unsigned)H && (unsigned)gc < (unsigned)W)
                    v = __ldg(src + gr * W + gc);
                dst[i] = v;
            }
        }
    }
    __syncthreads();

    const int row = row0 + ty;
    const int col = col0 + tx;
    const float* feb = fe + (size_t)b * C * plane + (size_t)row * W + col;

    // ---- Pass 1: accumulate squared distances for 9 neighbors over C ----
    float acc[9];
    #pragma unroll
    for (int k = 0; k < 9; ++k) acc[k] = 0.0f;

    #pragma unroll 4
    for (int c = 0; c < C; ++c) {
        float fv = __ldg(feb + (size_t)c * plane);
        const float* sp = smf + c * HALO_ELEMS + ty * WC + tx;  // halo (ty+dr, tx+dc)
        #pragma unroll
        for (int dr = 0; dr < 3; ++dr) {
            #pragma unroll
            for (int dc = 0; dc < 3; ++dc) {
                float d = sp[dr * WC + dc] - fv;
                acc[dr * 3 + dc] = fmaf(d, d, acc[dr * 3 + dc]);
            }
        }
    }

    // ---- Softmax over 9 neighbors of -sqrt(acc) ----
    float dist[9];
    float mn = 3.402823e38f;
    #pragma unroll
    for (int k = 0; k < 9; ++k) {
        dist[k] = sqrtf(acc[k]);
        mn = fminf(mn, dist[k]);
    }
    float wgt[9];
    float s = 0.0f;
    #pragma unroll
    for (int k = 0; k < 9; ++k) {
        wgt[k] = __expf(mn - dist[k]);
        s += wgt[k];
    }
    float inv = 1.0f / s;
    #pragma unroll
    for (int k = 0; k < 9; ++k) wgt[k] *= inv;

    // ---- Pass 2: weighted sum of patches + fe_lv, write output ----
    float* ob = out + (size_t)b * C * plane + (size_t)row * W + col;
    #pragma unroll 4
    for (int c = 0; c < C; ++c) {
        const float* sp = smf + c * HALO_ELEMS + ty * WC + tx;
        float acc2 = 0.0f;
        #pragma unroll
        for (int dr = 0; dr < 3; ++dr) {
            #pragma unroll
            for (int dc = 0; dc < 3; ++dc) {
                acc2 = fmaf(wgt[dr * 3 + dc], sp[dr * WC + dc], acc2);
            }
        }
        float fv = __ldg(feb + (size_t)c * plane);
        ob[(size_t)c * plane] = acc2 + fv;
    }
}

extern "C" void kernel_launch(void* const* d_in, const int* in_sizes, int n_in,
                              void* d_out, int out_size) {
    const float* fe = (const float*)d_in[0];  // fe_lv
    const float* fu = (const float*)d_in[1];  // fused_features
    float* out = (float*)d_out;

    static bool attr_set = false;
    if (!attr_set) {
        cudaFuncSetAttribute(refine_kernel,
                             cudaFuncAttributeMaxDynamicSharedMemorySize,
                             SMEM_BYTES);
        attr_set = true;
    }

    dim3 grid(W / TW, H / TH, 8);   // (4, 8, 8)
    dim3 block(32, 16);
    refine_kernel<<<grid, block, SMEM_BYTES>>>(fe, fu, out);
}